// round 16
// baseline (speedup 1.0000x reference)
#include <cuda_runtime.h>
#include <math.h>

#define FULLMASK 0xffffffffu
#define NTOK 64
#define PAST 4096
#define TOT  4100
#define OUT_OFF 262144
#define NEWK_ELEMS 67174400
#define KS 16
#define NSP 8                                   // KV splits

typedef unsigned long long ull;

// ---------------------- packed fp32x2 helpers (sm_103a) ---------------------
__device__ __forceinline__ ull pk2(float lo, float hi) {
    ull r;
    asm("mov.b64 %0, {%1, %2};" : "=l"(r) : "f"(lo), "f"(hi));
    return r;
}
__device__ __forceinline__ ull ffma2(ull a, ull b, ull c) {
    ull d;
    asm("fma.rn.f32x2 %0, %1, %2, %3;" : "=l"(d) : "l"(a), "l"(b), "l"(c));
    return d;
}
__device__ __forceinline__ float2 upk2(ull v) {
    float2 r;
    asm("mov.b64 {%0, %1}, %2;" : "=f"(r.x), "=f"(r.y) : "l"(v));
    return r;
}

// ------------------------- scratch (allocation-free) ------------------------
__device__ float g_part[KS * 64 * 6144];         // split-K partials
__device__ float g_q   [64 * 4096];              // roped Q, token-major
__device__ float g_attn[64 * 4096];              // attention output (pre w_o)
__device__ float g_knew[64 * 8 * 128];           // roped new K rows
__device__ float g_vnew[64 * 8 * 128];           // new V rows
__device__ float g_po  [128 * NSP * 32 * 128];   // per-(CTA,warp) partial O rows
__device__ float g_pl  [128 * NSP * 32];         // partial sums (additive)

// ------------------------------ split-K GEMM (R10, measured-best) -----------
__global__ __launch_bounds__(256) void gemm_splitk(
    const float* __restrict__ Ain, const float* __restrict__ W,
    int N, int useAttn)
{
    const float* A = useAttn ? g_attn : Ain;
    __shared__ __align__(16) float As[2][16][64];
    __shared__ __align__(16) float Bs[2][16][128];

    const int tid = threadIdx.x;
    const int n0  = blockIdx.x * 128;
    const int kbase = blockIdx.y * 256;          // Kchunk = 256, KS = 16

    const int lm = tid >> 2,  lk = (tid & 3) << 2;
    const int bk = tid >> 4,  bn = (tid & 15) << 3;

    const float* Ap = A + (size_t)lm * 4096 + kbase + lk;
    const float* Wp = W + (size_t)(kbase + bk) * N + n0 + bn;

    float4 ar  = *(const float4*)Ap;
    float4 br0 = *(const float4*)Wp;
    float4 br1 = *(const float4*)(Wp + 4);

    const int tm = (tid >> 5) << 3;
    const int tn = (tid & 31) << 2;

    ull acc[4][4];
    #pragma unroll
    for (int p = 0; p < 4; p++)
        #pragma unroll
        for (int j = 0; j < 4; j++) acc[p][j] = 0ull;

    for (int st = 0; st < 16; st++) {
        const int cur = st & 1;
        As[cur][lk + 0][lm] = ar.x;
        As[cur][lk + 1][lm] = ar.y;
        As[cur][lk + 2][lm] = ar.z;
        As[cur][lk + 3][lm] = ar.w;
        *(float4*)&Bs[cur][bk][bn]     = br0;
        *(float4*)&Bs[cur][bk][bn + 4] = br1;
        __syncthreads();
        if (st + 1 < 16) {
            ar  = *(const float4*)(Ap + (st + 1) * 16);
            br0 = *(const float4*)(Wp + (size_t)(st + 1) * 16 * N);
            br1 = *(const float4*)(Wp + (size_t)(st + 1) * 16 * N + 4);
        }
        #pragma unroll
        for (int k = 0; k < 16; k++) {
            float4 b4 = *(const float4*)&Bs[cur][k][tn];
            // adjacent-float pairs ARE packed f32x2 operands: one LDS.128 each
            ulonglong2 a01 = *(const ulonglong2*)&As[cur][k][tm];
            ulonglong2 a23 = *(const ulonglong2*)&As[cur][k][tm + 4];
            ull am[4] = {a01.x, a01.y, a23.x, a23.y};
            ull bx = pk2(b4.x, b4.x);
            ull by = pk2(b4.y, b4.y);
            ull bz = pk2(b4.z, b4.z);
            ull bw = pk2(b4.w, b4.w);
            #pragma unroll
            for (int p = 0; p < 4; p++) {
                acc[p][0] = ffma2(am[p], bx, acc[p][0]);
                acc[p][1] = ffma2(am[p], by, acc[p][1]);
                acc[p][2] = ffma2(am[p], bz, acc[p][2]);
                acc[p][3] = ffma2(am[p], bw, acc[p][3]);
            }
        }
    }

    float* out = g_part + (size_t)blockIdx.y * 64 * N;
    #pragma unroll
    for (int p = 0; p < 4; p++) {
        float2 c0 = upk2(acc[p][0]);
        float2 c1 = upk2(acc[p][1]);
        float2 c2 = upk2(acc[p][2]);
        float2 c3 = upk2(acc[p][3]);
        *(float4*)&out[(size_t)(tm + 2*p)     * N + n0 + tn] =
            make_float4(c0.x, c1.x, c2.x, c3.x);
        *(float4*)&out[(size_t)(tm + 2*p + 1) * N + n0 + tn] =
            make_float4(c0.y, c1.y, c2.y, c3.y);
    }
}

// ---------------- reduce split-K partials + RoPE + scatter ------------------
// RoPE inv_freq MUST use powf: angle = pos * inv_freq with pos ~ 4100
// amplifies ulp-level inv_freq differences to >1e-3 output error (R12 failure).
__global__ __launch_bounds__(256) void reduce_rope(
    const int* __restrict__ positions,
    float* __restrict__ out_newk, float* __restrict__ out_newv)
{
    int idx = blockIdx.x * 256 + threadIdx.x;    // 229376 total
    if (idx < 131072) {                          // Q rope pairs: 64*32*64
        int tok = idx >> 11;
        int rem = idx & 2047;
        int h = rem >> 6, d = rem & 63;
        int col = h * 128 + d;
        float v1 = 0.f, v2 = 0.f;
        #pragma unroll
        for (int ks = 0; ks < KS; ks++) {
            const float* p = g_part + (size_t)(ks * 64 + tok) * 6144;
            v1 += p[col];
            v2 += p[col + 64];
        }
        float pos = (float)positions[tok];
        float inv = powf(500000.0f, -(float)d * (1.0f / 64.0f));
        float sn, cs;
        sincosf(pos * inv, &sn, &cs);
        g_q[tok * 4096 + col]      = v1 * cs - v2 * sn;
        g_q[tok * 4096 + col + 64] = v2 * cs + v1 * sn;
    } else if (idx < 163840) {                   // K rope pairs: 64*8*64
        int j = idx - 131072;
        int tok = j >> 9;
        int rem = j & 511;
        int kv = rem >> 6, d = rem & 63;
        int col = 4096 + kv * 128 + d;
        float v1 = 0.f, v2 = 0.f;
        #pragma unroll
        for (int ks = 0; ks < KS; ks++) {
            const float* p = g_part + (size_t)(ks * 64 + tok) * 6144;
            v1 += p[col];
            v2 += p[col + 64];
        }
        float pos = (float)positions[tok];
        float inv = powf(500000.0f, -(float)d * (1.0f / 64.0f));
        float sn, cs;
        sincosf(pos * inv, &sn, &cs);
        float o1 = v1 * cs - v2 * sn;
        float o2 = v2 * cs + v1 * sn;
        g_knew[(tok * 8 + kv) * 128 + d]      = o1;
        g_knew[(tok * 8 + kv) * 128 + d + 64] = o2;
        int b = tok >> 2, s = tok & 3;
        size_t oo = ((size_t)(b * TOT + PAST + s) * 8 + kv) * 128 + d;
        out_newk[oo]      = o1;
        out_newk[oo + 64] = o2;
    } else {                                     // V passthrough: 64*8*128
        int j = idx - 163840;
        int tok = j >> 10;
        int rem = j & 1023;
        int kv = rem >> 7, d = rem & 127;
        int col = 5120 + kv * 128 + d;
        float v = 0.f;
        #pragma unroll
        for (int ks = 0; ks < KS; ks++)
            v += g_part[(size_t)(ks * 64 + tok) * 6144 + col];
        g_vnew[(tok * 8 + kv) * 128 + d] = v;
        int b = tok >> 2, s = tok & 3;
        out_newv[((size_t)(b * TOT + PAST + s) * 8 + kv) * 128 + d] = v;
    }
}

// ----------------- fused attention + KV-cache copy --------------------------
// grid = 128*NSP CTAs, 128 threads, 16-token tiles, single-buffered smem,
// 1-tile register prefetch (R10 measured-best config).
// NEW: blockIdx decode permuted so the 8 heads of one (b,split) are ADJACENT
// CTAs — co-resident, same token window, so their 512B/token reads+writes
// aggregate into 4KB-contiguous DRAM lines in the L2 window.
__device__ __forceinline__ void load_tile16(
    int gt, int tid, int b, int g,
    const float* __restrict__ pk, const float* __restrict__ pv,
    float4 kr[4], float4 vr[4])
{
    #pragma unroll
    for (int j = 0; j < 4; j++) {
        int idx = tid + j * 128;
        int t = idx >> 5, d4 = idx & 31;
        if (gt < 256) {
            size_t base = ((size_t)(b * PAST + gt * 16 + t) * 8 + g) * 128 + d4 * 4;
            kr[j] = *(const float4*)(pk + base);
            vr[j] = *(const float4*)(pv + base);
        } else if (t < 4) {
            size_t base = ((size_t)(b * 4 + t) * 8 + g) * 128 + d4 * 4;
            kr[j] = *(const float4*)(g_knew + base);
            vr[j] = *(const float4*)(g_vnew + base);
        } else {
            kr[j] = make_float4(0.f, 0.f, 0.f, 0.f);
            vr[j] = make_float4(0.f, 0.f, 0.f, 0.f);
        }
    }
}

__global__ __launch_bounds__(128) void attn_kernel(
    const float* __restrict__ past_k, const float* __restrict__ past_v,
    float* __restrict__ out_newk, float* __restrict__ out_newv)
{
    __shared__ float4 qsT[32][16];      // [d4][q] transposed Q
    __shared__ float4 ksm[16][32];      // [t][d4^t]
    __shared__ float4 vsm[16][32];
    __shared__ float2 p_sm[4][8][8];    // [warp][tloc][qloc] (p,p) pairs

    const int tid  = threadIdx.x;
    const int lane = tid & 31, w = tid >> 5;
    const int tg = w & 1, qh = w >> 1;
    const int tbase = tg * 8, qbase = qh * 8;
    const int tloc  = lane >> 2;                // 0..7
    const int qloc  = (lane & 3) << 1;          // 0,2,4,6
    const int q0 = qbase + qloc, q1 = q0 + 1;

    // head-adjacent decode: bid = (b*NSP + sp)*8 + g
    const int g  = blockIdx.x & 7;
    const int sp = (blockIdx.x >> 3) & (NSP - 1);
    const int b  = blockIdx.x >> 6;

    // load roped Q (transposed) for this (b,g): 16 rows x 128
    for (int i = tid; i < 512; i += 128) {
        int q = i >> 5, d4 = i & 31;
        int s = q >> 2, r = q & 3;
        qsT[d4][q] = *(const float4*)&g_q[(size_t)(b * 4 + s) * 4096 +
                                          (g * 4 + r) * 128 + d4 * 4];
    }

    float l0 = 0.f, l1 = 0.f;                   // per-lane partial sums
    ull Of[8][2];
    #pragma unroll
    for (int q = 0; q < 8; q++) { Of[q][0] = 0ull; Of[q][1] = 0ull; }

    const float scale = 0.08838834764831845f;   // 1/sqrt(128)
    const int nt = (sp == NSP - 1) ? 33 : 32;

    float4 kr[4], vr[4];
    load_tile16(sp * 32, tid, b, g, past_k, past_v, kr, vr);

    for (int lt = 0; lt < nt; lt++) {
        const int gt = sp * 32 + lt;            // 0..255 past, 256 = new rows
        if (lt) __syncthreads();
        #pragma unroll
        for (int j = 0; j < 4; j++) {
            int idx = tid + j * 128;
            int t = idx >> 5, d4 = idx & 31;
            ksm[t][d4 ^ t] = kr[j];
            vsm[t][d4 ^ t] = vr[j];
            if (gt < 256) {
                size_t ob = ((size_t)(b * TOT + gt * 16 + t) * 8 + g) * 128 + d4 * 4;
                __stcs((float4*)&out_newk[ob], kr[j]);   // streaming store
                __stcs((float4*)&out_newv[ob], vr[j]);
            }
        }
        __syncthreads();
        if (lt + 1 < nt) load_tile16(gt + 1, tid, b, g, past_k, past_v, kr, vr);

        // ---- scores: lane -> (token tbase+tloc) x (q0,q1) ----
        const int trow = tbase + tloc;
        ull s0a = 0ull, s0b = 0ull, s1a = 0ull, s1b = 0ull;
        #pragma unroll
        for (int d4 = 0; d4 < 32; d4++) {
            ulonglong2 kk = *(const ulonglong2*)&ksm[trow][d4 ^ trow];
            ulonglong2 qa = *(const ulonglong2*)&qsT[d4][q0];
            ulonglong2 qb = *(const ulonglong2*)&qsT[d4][q1];
            s0a = ffma2(qa.x, kk.x, s0a);
            s0b = ffma2(qa.y, kk.y, s0b);
            s1a = ffma2(qb.x, kk.x, s1a);
            s1b = ffma2(qb.y, kk.y, s1b);
        }
        float2 f0a = upk2(s0a), f0b = upk2(s0b);
        float2 f1a = upk2(s1a), f1b = upk2(s1b);
        float s0 = (f0a.x + f0a.y + f0b.x + f0b.y) * scale;
        float s1 = (f1a.x + f1a.y + f1b.x + f1b.y) * scale;
        if (gt == 256 && trow >= 4) { s0 = -1e30f; s1 = -1e30f; }

        // ---- direct exp (scores are small; no max shift needed) ----
        float p0 = __expf(s0), p1 = __expf(s1);
        l0 += p0;
        l1 += p1;

        // stage p (duplicated pairs)
        *(float4*)&p_sm[w][tloc][qloc] = make_float4(p0, p0, p1, p1);
        __syncwarp();

        // ---- PV: lane -> d4 fragment, all 8 q of this warp ----
        #pragma unroll
        for (int t = 0; t < 8; t++) {
            int row = tbase + t;
            ulonglong2 vv = *(const ulonglong2*)&vsm[row][lane ^ row];
            #pragma unroll
            for (int qp = 0; qp < 4; qp++) {
                ulonglong2 pp = *(const ulonglong2*)&p_sm[w][t][qp * 2];
                Of[2*qp][0]   = ffma2(pp.x, vv.x, Of[2*qp][0]);
                Of[2*qp][1]   = ffma2(pp.x, vv.y, Of[2*qp][1]);
                Of[2*qp+1][0] = ffma2(pp.y, vv.x, Of[2*qp+1][0]);
                Of[2*qp+1][1] = ffma2(pp.y, vv.y, Of[2*qp+1][1]);
            }
        }
        __syncwarp();                            // p_sm reuse next tile
    }

    // ---- reduce l across tloc lanes (once, end of kernel) ----
    #pragma unroll
    for (int off = 4; off <= 16; off <<= 1) {
        l0 += __shfl_xor_sync(FULLMASK, l0, off);
        l1 += __shfl_xor_sync(FULLMASK, l1, off);
    }

    // ---- write per-warp partials (indexed by blockIdx as-is) ----
    const int rowbase = (blockIdx.x * 4 + w) * 8;
    if (lane < 4) {
        g_pl[rowbase + qloc]     = l0;
        g_pl[rowbase + qloc + 1] = l1;
    }
    #pragma unroll
    for (int q = 0; q < 8; q++) {
        float2 lo = upk2(Of[q][0]), hi = upk2(Of[q][1]);
        *(float4*)&g_po[(size_t)(rowbase + q) * 128 + lane * 4] =
            make_float4(lo.x, lo.y, hi.x, hi.y);
    }
}

// --------------------- combine partials -> g_attn ---------------------------
// 16 additive partials per (bg, q): NSP splits x 2 token-groups.
// Row mapping matches attn_kernel's head-adjacent blockIdx decode:
//   blk(b, sp, g) = (b*NSP + sp)*8 + g
__global__ __launch_bounds__(256) void attn_combine()
{
    const int tid = threadIdx.x;
    const int lane = tid & 31, w = tid >> 5;
    const int bg = blockIdx.x;
    const int b = bg >> 3, g = bg & 7;

    #pragma unroll
    for (int qi = 0; qi < 2; qi++) {
        int q = 2 * w + qi;
        int wq = (q >> 3) * 2;                   // warp base for this qhalf
        float L = 0.f;
        float4 acc = make_float4(0.f, 0.f, 0.f, 0.f);
        #pragma unroll
        for (int i = 0; i < 2 * NSP; i++) {      // i = sp*2 + tg
            int sp = i >> 1, tg = i & 1;
            int blk = ((b * NSP + sp) << 3) | g;
            int row = (blk * 4 + wq + tg) * 8 + (q & 7);
            L += g_pl[row];
            float4 po = *(const float4*)&g_po[(size_t)row * 128 + lane * 4];
            acc.x += po.x; acc.y += po.y;
            acc.z += po.z; acc.w += po.w;
        }
        float inv = 1.f / L;
        acc.x *= inv; acc.y *= inv; acc.z *= inv; acc.w *= inv;
        int st = q >> 2, r = q & 3;
        *(float4*)&g_attn[(size_t)(b * 4 + st) * 4096 + (g * 4 + r) * 128 + lane * 4] = acc;
    }
}

// --------------------- final split-K reduce for output ----------------------
__global__ __launch_bounds__(256) void reduce_out(float* __restrict__ out)
{
    int idx = blockIdx.x * 256 + threadIdx.x;   // 262144
    int m = idx >> 12, n = idx & 4095;
    float v = 0.f;
    #pragma unroll
    for (int ks = 0; ks < KS; ks++)
        v += g_part[(size_t)(ks * 64 + m) * 4096 + n];
    out[idx] = v;
}

// -----------------------------------------------------------------------------
extern "C" void kernel_launch(void* const* d_in, const int* in_sizes, int n_in,
                              void* d_out, int out_size)
{
    const int*   positions = (const int*)  d_in[0];
    const float* hidden    = (const float*)d_in[1];
    const float* past_k    = (const float*)d_in[2];
    const float* past_v    = (const float*)d_in[3];
    const float* w_qkv     = (const float*)d_in[4];
    const float* w_o       = (const float*)d_in[5];

    float* out      = (float*)d_out;
    float* out_newk = out + OUT_OFF;
    float* out_newv = out_newk + NEWK_ELEMS;

    gemm_splitk<<<dim3(48, KS), 256>>>(hidden, w_qkv, 6144, 0);
    reduce_rope<<<896, 256>>>(positions, out_newk, out_newv);
    attn_kernel<<<128 * NSP, 128>>>(past_k, past_v, out_newk, out_newv);
    attn_combine<<<128, 256>>>();
    gemm_splitk<<<dim3(32, KS), 256>>>(nullptr, w_o, 4096, 1);
    reduce_out<<<1024, 256>>>(out);
}

// round 17
// speedup vs baseline: 1.0913x; 1.0913x over previous
#include <cuda_runtime.h>
#include <math.h>

#define FULLMASK 0xffffffffu
#define NTOK 64
#define PAST 4096
#define TOT  4100
#define OUT_OFF 262144
#define NEWK_ELEMS 67174400
#define KS 16
#define NSP 16                                  // KV splits (R16: 8 -> 16)

typedef unsigned long long ull;

// ---------------------- packed fp32x2 helpers (sm_103a) ---------------------
__device__ __forceinline__ ull pk2(float lo, float hi) {
    ull r;
    asm("mov.b64 %0, {%1, %2};" : "=l"(r) : "f"(lo), "f"(hi));
    return r;
}
__device__ __forceinline__ ull ffma2(ull a, ull b, ull c) {
    ull d;
    asm("fma.rn.f32x2 %0, %1, %2, %3;" : "=l"(d) : "l"(a), "l"(b), "l"(c));
    return d;
}
__device__ __forceinline__ float2 upk2(ull v) {
    float2 r;
    asm("mov.b64 {%0, %1}, %2;" : "=f"(r.x), "=f"(r.y) : "l"(v));
    return r;
}

// ------------------------- scratch (allocation-free) ------------------------
__device__ float g_part[KS * 64 * 6144];         // split-K partials
__device__ float g_q   [64 * 4096];              // roped Q, token-major
__device__ float g_attn[64 * 4096];              // attention output (pre w_o)
__device__ float g_knew[64 * 8 * 128];           // roped new K rows
__device__ float g_vnew[64 * 8 * 128];           // new V rows
__device__ float g_po  [128 * NSP * 32 * 128];   // per-(CTA,warp) partial O rows
__device__ float g_pl  [128 * NSP * 32];         // partial sums (additive)

// ------------------------------ split-K GEMM (R10, measured-best) -----------
__global__ __launch_bounds__(256) void gemm_splitk(
    const float* __restrict__ Ain, const float* __restrict__ W,
    int N, int useAttn)
{
    const float* A = useAttn ? g_attn : Ain;
    __shared__ __align__(16) float As[2][16][64];
    __shared__ __align__(16) float Bs[2][16][128];

    const int tid = threadIdx.x;
    const int n0  = blockIdx.x * 128;
    const int kbase = blockIdx.y * 256;          // Kchunk = 256, KS = 16

    const int lm = tid >> 2,  lk = (tid & 3) << 2;
    const int bk = tid >> 4,  bn = (tid & 15) << 3;

    const float* Ap = A + (size_t)lm * 4096 + kbase + lk;
    const float* Wp = W + (size_t)(kbase + bk) * N + n0 + bn;

    float4 ar  = *(const float4*)Ap;
    float4 br0 = *(const float4*)Wp;
    float4 br1 = *(const float4*)(Wp + 4);

    const int tm = (tid >> 5) << 3;
    const int tn = (tid & 31) << 2;

    ull acc[4][4];
    #pragma unroll
    for (int p = 0; p < 4; p++)
        #pragma unroll
        for (int j = 0; j < 4; j++) acc[p][j] = 0ull;

    for (int st = 0; st < 16; st++) {
        const int cur = st & 1;
        As[cur][lk + 0][lm] = ar.x;
        As[cur][lk + 1][lm] = ar.y;
        As[cur][lk + 2][lm] = ar.z;
        As[cur][lk + 3][lm] = ar.w;
        *(float4*)&Bs[cur][bk][bn]     = br0;
        *(float4*)&Bs[cur][bk][bn + 4] = br1;
        __syncthreads();
        if (st + 1 < 16) {
            ar  = *(const float4*)(Ap + (st + 1) * 16);
            br0 = *(const float4*)(Wp + (size_t)(st + 1) * 16 * N);
            br1 = *(const float4*)(Wp + (size_t)(st + 1) * 16 * N + 4);
        }
        #pragma unroll
        for (int k = 0; k < 16; k++) {
            float4 b4 = *(const float4*)&Bs[cur][k][tn];
            // adjacent-float pairs ARE packed f32x2 operands: one LDS.128 each
            ulonglong2 a01 = *(const ulonglong2*)&As[cur][k][tm];
            ulonglong2 a23 = *(const ulonglong2*)&As[cur][k][tm + 4];
            ull am[4] = {a01.x, a01.y, a23.x, a23.y};
            ull bx = pk2(b4.x, b4.x);
            ull by = pk2(b4.y, b4.y);
            ull bz = pk2(b4.z, b4.z);
            ull bw = pk2(b4.w, b4.w);
            #pragma unroll
            for (int p = 0; p < 4; p++) {
                acc[p][0] = ffma2(am[p], bx, acc[p][0]);
                acc[p][1] = ffma2(am[p], by, acc[p][1]);
                acc[p][2] = ffma2(am[p], bz, acc[p][2]);
                acc[p][3] = ffma2(am[p], bw, acc[p][3]);
            }
        }
    }

    float* out = g_part + (size_t)blockIdx.y * 64 * N;
    #pragma unroll
    for (int p = 0; p < 4; p++) {
        float2 c0 = upk2(acc[p][0]);
        float2 c1 = upk2(acc[p][1]);
        float2 c2 = upk2(acc[p][2]);
        float2 c3 = upk2(acc[p][3]);
        *(float4*)&out[(size_t)(tm + 2*p)     * N + n0 + tn] =
            make_float4(c0.x, c1.x, c2.x, c3.x);
        *(float4*)&out[(size_t)(tm + 2*p + 1) * N + n0 + tn] =
            make_float4(c0.y, c1.y, c2.y, c3.y);
    }
}

// ---------------- reduce split-K partials + RoPE + scatter ------------------
// RoPE inv_freq MUST use powf: angle = pos * inv_freq with pos ~ 4100
// amplifies ulp-level inv_freq differences to >1e-3 output error (R12 failure).
__global__ __launch_bounds__(256) void reduce_rope(
    const int* __restrict__ positions,
    float* __restrict__ out_newk, float* __restrict__ out_newv)
{
    int idx = blockIdx.x * 256 + threadIdx.x;    // 229376 total
    if (idx < 131072) {                          // Q rope pairs: 64*32*64
        int tok = idx >> 11;
        int rem = idx & 2047;
        int h = rem >> 6, d = rem & 63;
        int col = h * 128 + d;
        float v1 = 0.f, v2 = 0.f;
        #pragma unroll
        for (int ks = 0; ks < KS; ks++) {
            const float* p = g_part + (size_t)(ks * 64 + tok) * 6144;
            v1 += p[col];
            v2 += p[col + 64];
        }
        float pos = (float)positions[tok];
        float inv = powf(500000.0f, -(float)d * (1.0f / 64.0f));
        float sn, cs;
        sincosf(pos * inv, &sn, &cs);
        g_q[tok * 4096 + col]      = v1 * cs - v2 * sn;
        g_q[tok * 4096 + col + 64] = v2 * cs + v1 * sn;
    } else if (idx < 163840) {                   // K rope pairs: 64*8*64
        int j = idx - 131072;
        int tok = j >> 9;
        int rem = j & 511;
        int kv = rem >> 6, d = rem & 63;
        int col = 4096 + kv * 128 + d;
        float v1 = 0.f, v2 = 0.f;
        #pragma unroll
        for (int ks = 0; ks < KS; ks++) {
            const float* p = g_part + (size_t)(ks * 64 + tok) * 6144;
            v1 += p[col];
            v2 += p[col + 64];
        }
        float pos = (float)positions[tok];
        float inv = powf(500000.0f, -(float)d * (1.0f / 64.0f));
        float sn, cs;
        sincosf(pos * inv, &sn, &cs);
        float o1 = v1 * cs - v2 * sn;
        float o2 = v2 * cs + v1 * sn;
        g_knew[(tok * 8 + kv) * 128 + d]      = o1;
        g_knew[(tok * 8 + kv) * 128 + d + 64] = o2;
        int b = tok >> 2, s = tok & 3;
        size_t oo = ((size_t)(b * TOT + PAST + s) * 8 + kv) * 128 + d;
        out_newk[oo]      = o1;
        out_newk[oo + 64] = o2;
    } else {                                     // V passthrough: 64*8*128
        int j = idx - 163840;
        int tok = j >> 10;
        int rem = j & 1023;
        int kv = rem >> 7, d = rem & 127;
        int col = 5120 + kv * 128 + d;
        float v = 0.f;
        #pragma unroll
        for (int ks = 0; ks < KS; ks++)
            v += g_part[(size_t)(ks * 64 + tok) * 6144 + col];
        g_vnew[(tok * 8 + kv) * 128 + d] = v;
        int b = tok >> 2, s = tok & 3;
        out_newv[((size_t)(b * TOT + PAST + s) * 8 + kv) * 128 + d] = v;
    }
}

// ----------------- fused attention + KV-cache copy --------------------------
// grid = 128*NSP CTAs (bg*NSP+sp), 128 threads, 16-token tiles, single-buffered
// smem, 1-tile register prefetch. NSP=16: 16 tiles/CTA halves CTA duration ->
// halves the last-wave tail (makespan ~= work/capacity + T_CTA).
__device__ __forceinline__ void load_tile16(
    int gt, int tid, int b, int g,
    const float* __restrict__ pk, const float* __restrict__ pv,
    float4 kr[4], float4 vr[4])
{
    #pragma unroll
    for (int j = 0; j < 4; j++) {
        int idx = tid + j * 128;
        int t = idx >> 5, d4 = idx & 31;
        if (gt < 256) {
            size_t base = ((size_t)(b * PAST + gt * 16 + t) * 8 + g) * 128 + d4 * 4;
            kr[j] = *(const float4*)(pk + base);
            vr[j] = *(const float4*)(pv + base);
        } else if (t < 4) {
            size_t base = ((size_t)(b * 4 + t) * 8 + g) * 128 + d4 * 4;
            kr[j] = *(const float4*)(g_knew + base);
            vr[j] = *(const float4*)(g_vnew + base);
        } else {
            kr[j] = make_float4(0.f, 0.f, 0.f, 0.f);
            vr[j] = make_float4(0.f, 0.f, 0.f, 0.f);
        }
    }
}

__global__ __launch_bounds__(128) void attn_kernel(
    const float* __restrict__ past_k, const float* __restrict__ past_v,
    float* __restrict__ out_newk, float* __restrict__ out_newv)
{
    __shared__ float4 qsT[32][16];      // [d4][q] transposed Q
    __shared__ float4 ksm[16][32];      // [t][d4^t]
    __shared__ float4 vsm[16][32];
    __shared__ float2 p_sm[4][8][8];    // [warp][tloc][qloc] (p,p) pairs

    const int tid  = threadIdx.x;
    const int lane = tid & 31, w = tid >> 5;
    const int tg = w & 1, qh = w >> 1;
    const int tbase = tg * 8, qbase = qh * 8;
    const int tloc  = lane >> 2;                // 0..7
    const int qloc  = (lane & 3) << 1;          // 0,2,4,6
    const int q0 = qbase + qloc, q1 = q0 + 1;

    const int bg = blockIdx.x >> 4, sp = blockIdx.x & (NSP - 1);
    const int b = bg >> 3, g = bg & 7;

    // load roped Q (transposed) for this (b,g): 16 rows x 128
    for (int i = tid; i < 512; i += 128) {
        int q = i >> 5, d4 = i & 31;
        int s = q >> 2, r = q & 3;
        qsT[d4][q] = *(const float4*)&g_q[(size_t)(b * 4 + s) * 4096 +
                                          (g * 4 + r) * 128 + d4 * 4];
    }

    float l0 = 0.f, l1 = 0.f;                   // per-lane partial sums
    ull Of[8][2];
    #pragma unroll
    for (int q = 0; q < 8; q++) { Of[q][0] = 0ull; Of[q][1] = 0ull; }

    const float scale = 0.08838834764831845f;   // 1/sqrt(128)
    const int nt = (sp == NSP - 1) ? 17 : 16;   // 16 tiles/split; last += new rows

    float4 kr[4], vr[4];
    load_tile16(sp * 16, tid, b, g, past_k, past_v, kr, vr);

    for (int lt = 0; lt < nt; lt++) {
        const int gt = sp * 16 + lt;            // 0..255 past, 256 = new rows
        if (lt) __syncthreads();
        #pragma unroll
        for (int j = 0; j < 4; j++) {
            int idx = tid + j * 128;
            int t = idx >> 5, d4 = idx & 31;
            ksm[t][d4 ^ t] = kr[j];
            vsm[t][d4 ^ t] = vr[j];
            if (gt < 256) {
                size_t ob = ((size_t)(b * TOT + gt * 16 + t) * 8 + g) * 128 + d4 * 4;
                __stcs((float4*)&out_newk[ob], kr[j]);   // streaming store
                __stcs((float4*)&out_newv[ob], vr[j]);
            }
        }
        __syncthreads();
        if (lt + 1 < nt) load_tile16(gt + 1, tid, b, g, past_k, past_v, kr, vr);

        // ---- scores: lane -> (token tbase+tloc) x (q0,q1) ----
        const int trow = tbase + tloc;
        ull s0a = 0ull, s0b = 0ull, s1a = 0ull, s1b = 0ull;
        #pragma unroll
        for (int d4 = 0; d4 < 32; d4++) {
            ulonglong2 kk = *(const ulonglong2*)&ksm[trow][d4 ^ trow];
            ulonglong2 qa = *(const ulonglong2*)&qsT[d4][q0];
            ulonglong2 qb = *(const ulonglong2*)&qsT[d4][q1];
            s0a = ffma2(qa.x, kk.x, s0a);
            s0b = ffma2(qa.y, kk.y, s0b);
            s1a = ffma2(qb.x, kk.x, s1a);
            s1b = ffma2(qb.y, kk.y, s1b);
        }
        float2 f0a = upk2(s0a), f0b = upk2(s0b);
        float2 f1a = upk2(s1a), f1b = upk2(s1b);
        float s0 = (f0a.x + f0a.y + f0b.x + f0b.y) * scale;
        float s1 = (f1a.x + f1a.y + f1b.x + f1b.y) * scale;
        if (gt == 256 && trow >= 4) { s0 = -1e30f; s1 = -1e30f; }

        // ---- direct exp (scores are small; no max shift needed) ----
        float p0 = __expf(s0), p1 = __expf(s1);
        l0 += p0;
        l1 += p1;

        // stage p (duplicated pairs)
        *(float4*)&p_sm[w][tloc][qloc] = make_float4(p0, p0, p1, p1);
        __syncwarp();

        // ---- PV: lane -> d4 fragment, all 8 q of this warp ----
        #pragma unroll
        for (int t = 0; t < 8; t++) {
            int row = tbase + t;
            ulonglong2 vv = *(const ulonglong2*)&vsm[row][lane ^ row];
            #pragma unroll
            for (int qp = 0; qp < 4; qp++) {
                ulonglong2 pp = *(const ulonglong2*)&p_sm[w][t][qp * 2];
                Of[2*qp][0]   = ffma2(pp.x, vv.x, Of[2*qp][0]);
                Of[2*qp][1]   = ffma2(pp.x, vv.y, Of[2*qp][1]);
                Of[2*qp+1][0] = ffma2(pp.y, vv.x, Of[2*qp+1][0]);
                Of[2*qp+1][1] = ffma2(pp.y, vv.y, Of[2*qp+1][1]);
            }
        }
        __syncwarp();                            // p_sm reuse next tile
    }

    // ---- reduce l across tloc lanes (once, end of kernel) ----
    #pragma unroll
    for (int off = 4; off <= 16; off <<= 1) {
        l0 += __shfl_xor_sync(FULLMASK, l0, off);
        l1 += __shfl_xor_sync(FULLMASK, l1, off);
    }

    // ---- write per-warp partials ----
    const int rowbase = (blockIdx.x * 4 + w) * 8;
    if (lane < 4) {
        g_pl[rowbase + qloc]     = l0;
        g_pl[rowbase + qloc + 1] = l1;
    }
    #pragma unroll
    for (int q = 0; q < 8; q++) {
        float2 lo = upk2(Of[q][0]), hi = upk2(Of[q][1]);
        *(float4*)&g_po[(size_t)(rowbase + q) * 128 + lane * 4] =
            make_float4(lo.x, lo.y, hi.x, hi.y);
    }
}

// --------------------- combine partials -> g_attn ---------------------------
// 32 additive partials per (bg, q): NSP splits x 2 token-groups.
__global__ __launch_bounds__(256) void attn_combine()
{
    const int tid = threadIdx.x;
    const int lane = tid & 31, w = tid >> 5;
    const int bg = blockIdx.x;
    const int b = bg >> 3, g = bg & 7;

    #pragma unroll
    for (int qi = 0; qi < 2; qi++) {
        int q = 2 * w + qi;
        int wq = (q >> 3) * 2;                   // warp base for this qhalf
        float L = 0.f;
        float4 acc = make_float4(0.f, 0.f, 0.f, 0.f);
        #pragma unroll
        for (int i = 0; i < 2 * NSP; i++) {      // i = sp*2 + tg
            int sp = i >> 1, tg = i & 1;
            int row = ((bg * NSP + sp) * 4 + wq + tg) * 8 + (q & 7);
            L += g_pl[row];
            float4 po = *(const float4*)&g_po[(size_t)row * 128 + lane * 4];
            acc.x += po.x; acc.y += po.y;
            acc.z += po.z; acc.w += po.w;
        }
        float inv = 1.f / L;
        acc.x *= inv; acc.y *= inv; acc.z *= inv; acc.w *= inv;
        int st = q >> 2, r = q & 3;
        *(float4*)&g_attn[(size_t)(b * 4 + st) * 4096 + (g * 4 + r) * 128 + lane * 4] = acc;
    }
}

// --------------------- final split-K reduce for output ----------------------
__global__ __launch_bounds__(256) void reduce_out(float* __restrict__ out)
{
    int idx = blockIdx.x * 256 + threadIdx.x;   // 262144
    int m = idx >> 12, n = idx & 4095;
    float v = 0.f;
    #pragma unroll
    for (int ks = 0; ks < KS; ks++)
        v += g_part[(size_t)(ks * 64 + m) * 4096 + n];
    out[idx] = v;
}

// -----------------------------------------------------------------------------
extern "C" void kernel_launch(void* const* d_in, const int* in_sizes, int n_in,
                              void* d_out, int out_size)
{
    const int*   positions = (const int*)  d_in[0];
    const float* hidden    = (const float*)d_in[1];
    const float* past_k    = (const float*)d_in[2];
    const float* past_v    = (const float*)d_in[3];
    const float* w_qkv     = (const float*)d_in[4];
    const float* w_o       = (const float*)d_in[5];

    float* out      = (float*)d_out;
    float* out_newk = out + OUT_OFF;
    float* out_newv = out_newk + NEWK_ELEMS;

    gemm_splitk<<<dim3(48, KS), 256>>>(hidden, w_qkv, 6144, 0);
    reduce_rope<<<896, 256>>>(positions, out_newk, out_newv);
    attn_kernel<<<128 * NSP, 128>>>(past_k, past_v, out_newk, out_newv);
    attn_combine<<<128, 256>>>();
    gemm_splitk<<<dim3(32, KS), 256>>>(nullptr, w_o, 4096, 1);
    reduce_out<<<1024, 256>>>(out);
}